// round 14
// baseline (speedup 1.0000x reference)
#include <cuda_runtime.h>
#include <math.h>

#define N_NODES 50000
#define N_EDGES 800000
#define PER 8
#define CAP 64   // max in-degree slots; deg ~ Poisson(16), P(>=64) ~ 0

// ---- device scratch (static allocations only; zero-initialized at load) ----
__device__ int   g_cnt[N_NODES];                        // in-degree counter (self-resetting)
__device__ __align__(16) int g_esrc[N_NODES * CAP];     // binned src indices per dst
__device__ __align__(16) float g_Xs[N_NODES * 32];      // dinv[n] * x[n]  [N,4,8]
__device__ float g_Mz[128];                             // 0.5 * Wz @ LzW[:32]  -> [4][32]
__device__ float g_Mh[128];                             // Wh @ LhW[:32]        -> [4][32]
__device__ float g_cz[32];                              // 0.5 * (bz @ LzW[:32] + Lzb)
__device__ float g_ch[32];                              // bh @ LhW[:32] + Lhb
__device__ float g_probs[PER];                          // 0.5 * softmax(att)

__device__ __forceinline__ float tanh_fast(float v) {
    float r; asm("tanh.approx.f32 %0, %1;" : "=f"(r) : "f"(v)); return r;
}

// ------------------------------------------------------------------
// Bin edges by destination: one edge per thread. Block 0 lanes 0-31 also
// fold the gate weights (with 0.5 factors for the tanh-identity GRU).
__global__ void k_fill(const int* __restrict__ src, const int* __restrict__ dst,
                       const float* __restrict__ Wz, const float* __restrict__ bz,
                       const float* __restrict__ Wh, const float* __restrict__ bh,
                       const float* __restrict__ LzW, const float* __restrict__ Lzb,
                       const float* __restrict__ LhW, const float* __restrict__ Lhb,
                       const float* __restrict__ att) {
    if (blockIdx.x == 0 && threadIdx.x < 32) {
        int j = threadIdx.x;
        float cz = Lzb[j], ch = Lhb[j];
        #pragma unroll 8
        for (int k = 0; k < 32; k++) {
            cz += bz[k] * LzW[k * 32 + j];
            ch += bh[k] * LhW[k * 32 + j];
        }
        g_cz[j] = 0.5f * cz;           // az/2 folded into constants
        g_ch[j] = ch;
        #pragma unroll
        for (int f = 0; f < 4; f++) {
            float mz = 0.f, mh = 0.f;
            #pragma unroll 8
            for (int k = 0; k < 32; k++) {
                mz += Wz[f * 32 + k] * LzW[k * 32 + j];
                mh += Wh[f * 32 + k] * LhW[k * 32 + j];
            }
            g_Mz[f * 32 + j] = 0.5f * mz;
            g_Mh[f * 32 + j] = mh;
        }
        if (j == 0) {
            float m = att[0];
            for (int p = 1; p < PER; p++) m = fmaxf(m, att[p]);
            float s = 0.f, e[PER];
            for (int p = 0; p < PER; p++) { e[p] = expf(att[p] - m); s += e[p]; }
            for (int p = 0; p < PER; p++) g_probs[p] = 0.5f * e[p] / s;  // 0.5 from sigmoid identity
        }
    }

    int e = blockIdx.x * blockDim.x + threadIdx.x;
    if (e >= N_EDGES) return;
    int s = __ldg(&src[e]);
    int d = __ldg(&dst[e]);
    int pos = atomicAdd(&g_cnt[d], 1);
    if (pos < CAP) g_esrc[d * CAP + pos] = s;
}

// ------------------------------------------------------------------
// Pre-scale: g_Xs[n] = (deg[n]+1)^{-1/2} * x[n].  8 threads per node.
__global__ void k_scale(const float* __restrict__ x) {
    int i = blockIdx.x * blockDim.x + threadIdx.x;
    int n = i >> 3;
    int q = i & 7;
    if (n >= N_NODES) return;
    float dn = rsqrtf((float)g_cnt[n] + 1.0f);
    float4 v = reinterpret_cast<const float4*>(x)[n * 8 + q];
    v.x *= dn; v.y *= dn; v.z *= dn; v.w *= dn;
    reinterpret_cast<float4*>(g_Xs)[n * 8 + q] = v;
}

// ------------------------------------------------------------------
// Fused gather + GRU + attention + output.  8 lanes per node.
// GRU runs as two channel-half passes so only half the gate weights are
// register-resident at a time -> fits 50 regs -> 5 blocks/SM (62.5% occ).
__global__ void __launch_bounds__(256, 5)
k_fused(const float* __restrict__ outW, const float* __restrict__ outb,
        float* __restrict__ out) {
    __shared__ float sMz[128], sMh[128], scz[32], sch[32], sp[PER], sOW[256], sOb[PER];
    int t = threadIdx.x;   // block 256
    if (t < 128) { sMz[t] = g_Mz[t]; sMh[t] = g_Mh[t]; }
    if (t < 32)  { scz[t] = g_cz[t]; sch[t] = g_ch[t]; }
    if (t < PER) { sp[t] = g_probs[t]; sOb[t] = outb[t]; }
    sOW[t] = outW[t];
    __syncthreads();

    int gi = blockIdx.x * blockDim.x + t;
    int n_raw = gi >> 3;
    bool live = (n_raw < N_NODES);
    int n = live ? n_raw : (N_NODES - 1);        // clamp: keep warp uniform for shfl
    int w = t & 31;                              // lane in warp
    int q = w & 7;                               // lane in 8-group
    int gbase = w & ~7;                          // group base lane

    // ---- gather: lane q owns float4 chunk q of the 32-float row ----
    int cnt = g_cnt[n];
    int deg = cnt > CAP ? CAP : cnt;
    const int* row = &g_esrc[n * CAP];
    const float4* xs4 = reinterpret_cast<const float4*>(g_Xs);

    float4 acc = xs4[n * 8 + q];                 // self-loop term (pre-scaled)
    int nq = deg >> 2;                           // full quads
    #define PROC_QUAD(s4)                                            \
        do {                                                          \
            float4 v0 = xs4[(s4).x * 8 + q];                          \
            float4 v1 = xs4[(s4).y * 8 + q];                          \
            float4 v2 = xs4[(s4).z * 8 + q];                          \
            float4 v3 = xs4[(s4).w * 8 + q];                          \
            acc.x += (v0.x + v1.x) + (v2.x + v3.x);                   \
            acc.y += (v0.y + v1.y) + (v2.y + v3.y);                   \
            acc.z += (v0.z + v1.z) + (v2.z + v3.z);                   \
            acc.w += (v0.w + v1.w) + (v2.w + v3.w);                   \
        } while (0)
    if (nq == 1) {
        int4 a = *reinterpret_cast<const int4*>(row);
        PROC_QUAD(a);
    } else if (nq >= 2) {                        // depth-2 index prefetch
        int4 a = *reinterpret_cast<const int4*>(row);
        int4 b = *reinterpret_cast<const int4*>(row + 4);
        for (int i = 2; i < nq; i++) {
            int4 c = *reinterpret_cast<const int4*>(row + i * 4);
            PROC_QUAD(a);
            a = b; b = c;
        }
        PROC_QUAD(a);
        PROC_QUAD(b);
    }
    for (int e = nq << 2; e < deg; e++) {
        int s = row[e];
        float4 v = xs4[s * 8 + q];
        acc.x += v.x; acc.y += v.y; acc.z += v.z; acc.w += v.w;
    }
    #undef PROC_QUAD
    // reset counter for the next graph replay (only the owner group reads cnt[n]
    // in this kernel; k_scale, the only other reader, has already completed)
    if (live && q == 0) g_cnt[n] = 0;

    float dn = rsqrtf((float)cnt + 1.0f);
    acc.x *= dn; acc.y *= dn; acc.z *= dn; acc.w *= dn;
    // acc = yf[4q .. 4q+3] of row layout [f=0..3][p=0..7]

    int j0 = q * 4;
    float o[PER];
    #pragma unroll
    for (int k = 0; k < PER; k++) o[k] = sOb[k] * 0.125f;   // split bias so 8-lane sum = bias

    // ---- GRU in two channel-half passes (2 channels each) ----
    #pragma unroll
    for (int half = 0; half < 2; half++) {
        int jb = j0 + half * 2;
        float wMz[4][2], wMh[4][2], wcz[2], wch[2];
        #pragma unroll
        for (int i = 0; i < 2; i++) {
            wcz[i] = scz[jb + i];
            wch[i] = sch[jb + i];
            #pragma unroll
            for (int f = 0; f < 4; f++) {
                wMz[f][i] = sMz[f * 32 + jb + i];
                wMh[f][i] = sMh[f * 32 + jb + i];
            }
        }
        float Hacc[2] = {0.f, 0.f};
        #pragma unroll
        for (int p = 0; p < PER; p++) {
            float csel = (p & 3) == 0 ? acc.x : (p & 3) == 1 ? acc.y : (p & 3) == 2 ? acc.z : acc.w;
            int off = p >> 2;
            float y0 = __shfl_sync(0xffffffffu, csel, gbase + 0 + off);
            float y1 = __shfl_sync(0xffffffffu, csel, gbase + 2 + off);
            float y2 = __shfl_sync(0xffffffffu, csel, gbase + 4 + off);
            float y3 = __shfl_sync(0xffffffffu, csel, gbase + 6 + off);
            float pw = sp[p];   // = softmax(att)[p] / 2
            #pragma unroll
            for (int i = 0; i < 2; i++) {
                float azh = wcz[i] + y0 * wMz[0][i] + y1 * wMz[1][i] + y2 * wMz[2][i] + y3 * wMz[3][i];
                float ah  = wch[i] + y0 * wMh[0][i] + y1 * wMh[1][i] + y2 * wMh[2][i] + y3 * wMh[3][i];
                // sigmoid(-az)*tanh(ah) = 0.5*(1 - tanh(az/2))*tanh(ah); 0.5 in pw
                float t1 = tanh_fast(azh);
                float t2 = tanh_fast(ah);
                Hacc[i] += pw * (t2 - t1 * t2);
            }
        }
        #pragma unroll
        for (int i = 0; i < 2; i++) {
            float r = fmaxf(Hacc[i], 0.0f);
            #pragma unroll
            for (int k = 0; k < PER; k++) o[k] += r * sOW[(jb + i) * 8 + k];
        }
    }

    // ---- 8-lane butterfly, lane q stores out[n*8+q] ----
    #pragma unroll
    for (int m = 1; m <= 4; m <<= 1) {
        #pragma unroll
        for (int k = 0; k < PER; k++)
            o[k] += __shfl_xor_sync(0xffffffffu, o[k], m);
    }
    float val = (q & 4) ? ((q & 2) ? ((q & 1) ? o[7] : o[6]) : ((q & 1) ? o[5] : o[4]))
                        : ((q & 2) ? ((q & 1) ? o[3] : o[2]) : ((q & 1) ? o[1] : o[0]));
    if (live) out[n * 8 + q] = val;
}

// ------------------------------------------------------------------
extern "C" void kernel_launch(void* const* d_in, const int* in_sizes, int n_in,
                              void* d_out, int out_size) {
    const float* x   = (const float*)d_in[0];
    const int* ei    = (const int*)d_in[1];
    const float* Wz  = (const float*)d_in[2];
    const float* bz  = (const float*)d_in[3];
    const float* Wh  = (const float*)d_in[6];
    const float* bh  = (const float*)d_in[7];
    const float* LzW = (const float*)d_in[8];
    const float* Lzb = (const float*)d_in[9];
    const float* LhW = (const float*)d_in[12];
    const float* Lhb = (const float*)d_in[13];
    const float* att = (const float*)d_in[14];
    const float* outW = (const float*)d_in[15];
    const float* outb = (const float*)d_in[16];
    float* out = (float*)d_out;

    const int* src = ei;             // edge_index[0,:]
    const int* dst = ei + N_EDGES;   // edge_index[1,:]

    k_fill<<<(N_EDGES + 255) / 256, 256>>>(src, dst, Wz, bz, Wh, bh,
                                           LzW, Lzb, LhW, Lhb, att);
    k_scale<<<(N_NODES * 8 + 255) / 256, 256>>>(x);
    k_fused<<<(N_NODES * 8 + 255) / 256, 256>>>(outW, outb, out);
}

// round 15
// speedup vs baseline: 1.3894x; 1.3894x over previous
#include <cuda_runtime.h>
#include <math.h>

#define N_NODES 50000
#define N_EDGES 800000
#define PER 8
#define CAP 64   // max in-degree slots; deg ~ Poisson(16), P(>=64) ~ 0

// ---- device scratch (static allocations only; zero-initialized at load) ----
__device__ int   g_cnt[N_NODES];                        // in-degree counter (self-resetting)
__device__ __align__(16) int g_esrc[N_NODES * CAP];     // binned src indices per dst
__device__ __align__(16) float g_Xs[N_NODES * 32];      // dinv[n] * x[n]  [N,4,8]
__device__ float g_Mz[128];                             // 0.5 * Wz @ LzW[:32]  -> [4][32]
__device__ float g_Mh[128];                             // Wh @ LhW[:32]        -> [4][32]
__device__ float g_cz[32];                              // 0.5 * (bz @ LzW[:32] + Lzb)
__device__ float g_ch[32];                              // bh @ LhW[:32] + Lhb
__device__ float g_probs[PER];                          // 0.5 * softmax(att)

__device__ __forceinline__ float tanh_fast(float v) {
    float r; asm("tanh.approx.f32 %0, %1;" : "=f"(r) : "f"(v)); return r;
}

// ------------------------------------------------------------------
// Bin edges by destination: one edge per thread (best-measured variant).
// Block 0 lanes 0-31 also fold the gate weights (with 0.5 factors for the
// tanh-identity GRU).
__global__ void k_fill(const int* __restrict__ src, const int* __restrict__ dst,
                       const float* __restrict__ Wz, const float* __restrict__ bz,
                       const float* __restrict__ Wh, const float* __restrict__ bh,
                       const float* __restrict__ LzW, const float* __restrict__ Lzb,
                       const float* __restrict__ LhW, const float* __restrict__ Lhb,
                       const float* __restrict__ att) {
    if (blockIdx.x == 0 && threadIdx.x < 32) {
        int j = threadIdx.x;
        float cz = Lzb[j], ch = Lhb[j];
        #pragma unroll 8
        for (int k = 0; k < 32; k++) {
            cz += bz[k] * LzW[k * 32 + j];
            ch += bh[k] * LhW[k * 32 + j];
        }
        g_cz[j] = 0.5f * cz;           // az/2 folded into constants
        g_ch[j] = ch;
        #pragma unroll
        for (int f = 0; f < 4; f++) {
            float mz = 0.f, mh = 0.f;
            #pragma unroll 8
            for (int k = 0; k < 32; k++) {
                mz += Wz[f * 32 + k] * LzW[k * 32 + j];
                mh += Wh[f * 32 + k] * LhW[k * 32 + j];
            }
            g_Mz[f * 32 + j] = 0.5f * mz;
            g_Mh[f * 32 + j] = mh;
        }
        if (j == 0) {
            float m = att[0];
            for (int p = 1; p < PER; p++) m = fmaxf(m, att[p]);
            float s = 0.f, e[PER];
            for (int p = 0; p < PER; p++) { e[p] = expf(att[p] - m); s += e[p]; }
            for (int p = 0; p < PER; p++) g_probs[p] = 0.5f * e[p] / s;  // 0.5 from sigmoid identity
        }
    }

    int e = blockIdx.x * blockDim.x + threadIdx.x;
    if (e >= N_EDGES) return;
    int s = __ldg(&src[e]);
    int d = __ldg(&dst[e]);
    int pos = atomicAdd(&g_cnt[d], 1);
    if (pos < CAP) g_esrc[d * CAP + pos] = s;
}

// ------------------------------------------------------------------
// Pre-scale: g_Xs[n] = (deg[n]+1)^{-1/2} * x[n].  8 threads per node.
__global__ void k_scale(const float* __restrict__ x) {
    int i = blockIdx.x * blockDim.x + threadIdx.x;
    int n = i >> 3;
    int q = i & 7;
    if (n >= N_NODES) return;
    float dn = rsqrtf((float)g_cnt[n] + 1.0f);
    float4 v = reinterpret_cast<const float4*>(x)[n * 8 + q];
    v.x *= dn; v.y *= dn; v.z *= dn; v.w *= dn;
    reinterpret_cast<float4*>(g_Xs)[n * 8 + q] = v;
}

// ------------------------------------------------------------------
// Fused gather + GRU + attention + output.  8 lanes per node.
// Gather loop is software-pipelined: quad i+1's index vector is loaded
// before quad i's four gathers are issued (halves the exposed chain).
__global__ void __launch_bounds__(256, 4)
k_fused(const float* __restrict__ outW, const float* __restrict__ outb,
        float* __restrict__ out) {
    __shared__ float sMz[128], sMh[128], scz[32], sch[32], sp[PER], sOW[256], sOb[PER];
    int t = threadIdx.x;   // block 256
    if (t < 128) { sMz[t] = g_Mz[t]; sMh[t] = g_Mh[t]; }
    if (t < 32)  { scz[t] = g_cz[t]; sch[t] = g_ch[t]; }
    if (t < PER) { sp[t] = g_probs[t]; sOb[t] = outb[t]; }
    sOW[t] = outW[t];
    __syncthreads();

    int gi = blockIdx.x * blockDim.x + t;
    int n_raw = gi >> 3;
    bool live = (n_raw < N_NODES);
    int n = live ? n_raw : (N_NODES - 1);        // clamp: keep warp uniform for shfl
    int w = t & 31;                              // lane in warp
    int q = w & 7;                               // lane in 8-group
    int gbase = w & ~7;                          // group base lane

    // ---- gather: lane q owns float4 chunk q of the 32-float row ----
    int cnt = g_cnt[n];
    int deg = cnt > CAP ? CAP : cnt;
    const int* row = &g_esrc[n * CAP];
    const float4* xs4 = reinterpret_cast<const float4*>(g_Xs);

    float4 acc = xs4[n * 8 + q];                 // self-loop term (pre-scaled)
    int nq = deg >> 2;                           // full quads
    if (nq > 0) {
        int4 s4 = *reinterpret_cast<const int4*>(row);       // 16B-aligned (CAP=64)
        for (int i = 1; i < nq; i++) {
            int4 nxt = *reinterpret_cast<const int4*>(row + i * 4);  // prefetch next quad
            float4 v0 = xs4[s4.x * 8 + q];
            float4 v1 = xs4[s4.y * 8 + q];
            float4 v2 = xs4[s4.z * 8 + q];
            float4 v3 = xs4[s4.w * 8 + q];
            acc.x += (v0.x + v1.x) + (v2.x + v3.x);
            acc.y += (v0.y + v1.y) + (v2.y + v3.y);
            acc.z += (v0.z + v1.z) + (v2.z + v3.z);
            acc.w += (v0.w + v1.w) + (v2.w + v3.w);
            s4 = nxt;
        }
        float4 v0 = xs4[s4.x * 8 + q];
        float4 v1 = xs4[s4.y * 8 + q];
        float4 v2 = xs4[s4.z * 8 + q];
        float4 v3 = xs4[s4.w * 8 + q];
        acc.x += (v0.x + v1.x) + (v2.x + v3.x);
        acc.y += (v0.y + v1.y) + (v2.y + v3.y);
        acc.z += (v0.z + v1.z) + (v2.z + v3.z);
        acc.w += (v0.w + v1.w) + (v2.w + v3.w);
    }
    for (int e = nq << 2; e < deg; e++) {
        int s = row[e];
        float4 v = xs4[s * 8 + q];
        acc.x += v.x; acc.y += v.y; acc.z += v.z; acc.w += v.w;
    }
    // reset counter for the next graph replay (only the owner group reads cnt[n]
    // in this kernel; k_scale, the only other reader, has already completed)
    if (live && q == 0) g_cnt[n] = 0;

    float dn = rsqrtf((float)cnt + 1.0f);
    acc.x *= dn; acc.y *= dn; acc.z *= dn; acc.w *= dn;
    // acc = yf[4q .. 4q+3] of row layout [f=0..3][p=0..7]

    // ---- preload this lane's 4 hidden-channel weight columns ----
    int j0 = q * 4;
    float rMz[4][4], rMh[4][4], rcz[4], rch[4];
    #pragma unroll
    for (int i = 0; i < 4; i++) {
        rcz[i] = scz[j0 + i];
        rch[i] = sch[j0 + i];
        #pragma unroll
        for (int f = 0; f < 4; f++) {
            rMz[f][i] = sMz[f * 32 + j0 + i];
            rMh[f][i] = sMh[f * 32 + j0 + i];
        }
    }

    float Hacc[4] = {0.f, 0.f, 0.f, 0.f};
    #pragma unroll
    for (int p = 0; p < PER; p++) {
        float csel = (p & 3) == 0 ? acc.x : (p & 3) == 1 ? acc.y : (p & 3) == 2 ? acc.z : acc.w;
        int off = p >> 2;
        float y0 = __shfl_sync(0xffffffffu, csel, gbase + 0 + off);
        float y1 = __shfl_sync(0xffffffffu, csel, gbase + 2 + off);
        float y2 = __shfl_sync(0xffffffffu, csel, gbase + 4 + off);
        float y3 = __shfl_sync(0xffffffffu, csel, gbase + 6 + off);
        float pw = sp[p];   // = softmax(att)[p] / 2
        #pragma unroll
        for (int i = 0; i < 4; i++) {
            // azh = az/2 (0.5 folded into rMz/rcz); ah unscaled
            float azh = rcz[i] + y0 * rMz[0][i] + y1 * rMz[1][i] + y2 * rMz[2][i] + y3 * rMz[3][i];
            float ah  = rch[i] + y0 * rMh[0][i] + y1 * rMh[1][i] + y2 * rMh[2][i] + y3 * rMh[3][i];
            // sigmoid(-az)*tanh(ah) = 0.5*(1 - tanh(az/2))*tanh(ah); 0.5 folded into pw
            float t1 = tanh_fast(azh);
            float t2 = tanh_fast(ah);
            Hacc[i] += pw * (t2 - t1 * t2);
        }
    }

    // ---- output: partial o[8] over this lane's 4 channels, then 8-lane butterfly ----
    float o[PER];
    #pragma unroll
    for (int k = 0; k < PER; k++) o[k] = sOb[k] * 0.125f;   // split bias so 8-lane sum = bias
    #pragma unroll
    for (int i = 0; i < 4; i++) {
        float r = fmaxf(Hacc[i], 0.0f);
        #pragma unroll
        for (int k = 0; k < PER; k++) o[k] += r * sOW[(j0 + i) * 8 + k];
    }
    #pragma unroll
    for (int m = 1; m <= 4; m <<= 1) {
        #pragma unroll
        for (int k = 0; k < PER; k++)
            o[k] += __shfl_xor_sync(0xffffffffu, o[k], m);
    }
    float val = (q & 4) ? ((q & 2) ? ((q & 1) ? o[7] : o[6]) : ((q & 1) ? o[5] : o[4]))
                        : ((q & 2) ? ((q & 1) ? o[3] : o[2]) : ((q & 1) ? o[1] : o[0]));
    if (live) out[n * 8 + q] = val;
}

// ------------------------------------------------------------------
extern "C" void kernel_launch(void* const* d_in, const int* in_sizes, int n_in,
                              void* d_out, int out_size) {
    const float* x   = (const float*)d_in[0];
    const int* ei    = (const int*)d_in[1];
    const float* Wz  = (const float*)d_in[2];
    const float* bz  = (const float*)d_in[3];
    const float* Wh  = (const float*)d_in[6];
    const float* bh  = (const float*)d_in[7];
    const float* LzW = (const float*)d_in[8];
    const float* Lzb = (const float*)d_in[9];
    const float* LhW = (const float*)d_in[12];
    const float* Lhb = (const float*)d_in[13];
    const float* att = (const float*)d_in[14];
    const float* outW = (const float*)d_in[15];
    const float* outb = (const float*)d_in[16];
    float* out = (float*)d_out;

    const int* src = ei;             // edge_index[0,:]
    const int* dst = ei + N_EDGES;   // edge_index[1,:]

    k_fill<<<(N_EDGES + 255) / 256, 256>>>(src, dst, Wz, bz, Wh, bh,
                                           LzW, Lzb, LhW, Lhb, att);
    k_scale<<<(N_NODES * 8 + 255) / 256, 256>>>(x);
    k_fused<<<(N_NODES * 8 + 255) / 256, 256>>>(outW, outb, out);
}

// round 16
// speedup vs baseline: 1.3956x; 1.0045x over previous
#include <cuda_runtime.h>
#include <math.h>

#define N_NODES 50000
#define N_EDGES 800000
#define PER 8
#define CAP 64   // max in-degree slots; deg ~ Poisson(16), P(>=64) ~ 0

// ---- device scratch (static allocations only; zero-initialized at load) ----
__device__ int   g_cnt[N_NODES];                        // in-degree counter (self-resetting)
__device__ __align__(16) int g_esrc[N_NODES * CAP];     // binned src indices per dst
__device__ __align__(16) float g_Xs[N_NODES * 32];      // dinv[n] * x[n]  [N,4,8]
__device__ float g_Mz[128];                             // 0.5 * Wz @ LzW[:32]  -> [4][32]
__device__ float g_Mh[128];                             // Wh @ LhW[:32]        -> [4][32]
__device__ float g_cz[32];                              // 0.5 * (bz @ LzW[:32] + Lzb)
__device__ float g_ch[32];                              // bh @ LhW[:32] + Lhb
__device__ float g_probs[PER];                          // 0.5 * softmax(att)

__device__ __forceinline__ float tanh_fast(float v) {
    float r; asm("tanh.approx.f32 %0, %1;" : "=f"(r) : "f"(v)); return r;
}

// ------------------------------------------------------------------
// Bin edges by destination: one edge per thread (best-measured variant).
// Block 0 lanes 0-31 also fold the gate weights (with 0.5 factors for the
// tanh-identity GRU).
__global__ void k_fill(const int* __restrict__ src, const int* __restrict__ dst,
                       const float* __restrict__ Wz, const float* __restrict__ bz,
                       const float* __restrict__ Wh, const float* __restrict__ bh,
                       const float* __restrict__ LzW, const float* __restrict__ Lzb,
                       const float* __restrict__ LhW, const float* __restrict__ Lhb,
                       const float* __restrict__ att) {
    if (blockIdx.x == 0 && threadIdx.x < 32) {
        int j = threadIdx.x;
        float cz = Lzb[j], ch = Lhb[j];
        #pragma unroll 8
        for (int k = 0; k < 32; k++) {
            cz += bz[k] * LzW[k * 32 + j];
            ch += bh[k] * LhW[k * 32 + j];
        }
        g_cz[j] = 0.5f * cz;           // az/2 folded into constants
        g_ch[j] = ch;
        #pragma unroll
        for (int f = 0; f < 4; f++) {
            float mz = 0.f, mh = 0.f;
            #pragma unroll 8
            for (int k = 0; k < 32; k++) {
                mz += Wz[f * 32 + k] * LzW[k * 32 + j];
                mh += Wh[f * 32 + k] * LhW[k * 32 + j];
            }
            g_Mz[f * 32 + j] = 0.5f * mz;
            g_Mh[f * 32 + j] = mh;
        }
        if (j == 0) {
            float m = att[0];
            for (int p = 1; p < PER; p++) m = fmaxf(m, att[p]);
            float s = 0.f, e[PER];
            for (int p = 0; p < PER; p++) { e[p] = expf(att[p] - m); s += e[p]; }
            for (int p = 0; p < PER; p++) g_probs[p] = 0.5f * e[p] / s;  // 0.5 from sigmoid identity
        }
    }

    int e = blockIdx.x * blockDim.x + threadIdx.x;
    if (e >= N_EDGES) return;
    int s = __ldg(&src[e]);
    int d = __ldg(&dst[e]);
    int pos = atomicAdd(&g_cnt[d], 1);
    if (pos < CAP) g_esrc[d * CAP + pos] = s;
}

// ------------------------------------------------------------------
// Pre-scale: g_Xs[n] = (deg[n]+1)^{-1/2} * x[n].  8 threads per node.
__global__ void k_scale(const float* __restrict__ x) {
    int i = blockIdx.x * blockDim.x + threadIdx.x;
    int n = i >> 3;
    int q = i & 7;
    if (n >= N_NODES) return;
    float dn = rsqrtf((float)g_cnt[n] + 1.0f);
    float4 v = reinterpret_cast<const float4*>(x)[n * 8 + q];
    v.x *= dn; v.y *= dn; v.z *= dn; v.w *= dn;
    reinterpret_cast<float4*>(g_Xs)[n * 8 + q] = v;
}

// ------------------------------------------------------------------
// Fused gather + GRU + attention + output.  8 lanes per node.
// Gather processes 8 edges/iteration (MLP=8) with both index quads
// software-pipelined one block ahead. The GRU phase's ~56-reg live set is
// the register ceiling; the deeper gather stays under it (disjoint phases).
__global__ void __launch_bounds__(256, 4)
k_fused(const float* __restrict__ outW, const float* __restrict__ outb,
        float* __restrict__ out) {
    __shared__ float sMz[128], sMh[128], scz[32], sch[32], sp[PER], sOW[256], sOb[PER];
    int t = threadIdx.x;   // block 256
    if (t < 128) { sMz[t] = g_Mz[t]; sMh[t] = g_Mh[t]; }
    if (t < 32)  { scz[t] = g_cz[t]; sch[t] = g_ch[t]; }
    if (t < PER) { sp[t] = g_probs[t]; sOb[t] = outb[t]; }
    sOW[t] = outW[t];
    __syncthreads();

    int gi = blockIdx.x * blockDim.x + t;
    int n_raw = gi >> 3;
    bool live = (n_raw < N_NODES);
    int n = live ? n_raw : (N_NODES - 1);        // clamp: keep warp uniform for shfl
    int w = t & 31;                              // lane in warp
    int q = w & 7;                               // lane in 8-group
    int gbase = w & ~7;                          // group base lane

    // ---- gather: lane q owns float4 chunk q of the 32-float row ----
    int cnt = g_cnt[n];
    int deg = cnt > CAP ? CAP : cnt;
    const int* row = &g_esrc[n * CAP];
    const float4* xs4 = reinterpret_cast<const float4*>(g_Xs);

    float4 acc = xs4[n * 8 + q];                 // self-loop term (pre-scaled)
    float4 accB = make_float4(0.f, 0.f, 0.f, 0.f);

    #define PROC8(sa, sb)                                             \
        do {                                                           \
            float4 v0 = xs4[(sa).x * 8 + q];                           \
            float4 v1 = xs4[(sa).y * 8 + q];                           \
            float4 v2 = xs4[(sa).z * 8 + q];                           \
            float4 v3 = xs4[(sa).w * 8 + q];                           \
            float4 v4 = xs4[(sb).x * 8 + q];                           \
            float4 v5 = xs4[(sb).y * 8 + q];                           \
            float4 v6 = xs4[(sb).z * 8 + q];                           \
            float4 v7 = xs4[(sb).w * 8 + q];                           \
            acc.x  += (v0.x + v1.x) + (v2.x + v3.x);                   \
            acc.y  += (v0.y + v1.y) + (v2.y + v3.y);                   \
            acc.z  += (v0.z + v1.z) + (v2.z + v3.z);                   \
            acc.w  += (v0.w + v1.w) + (v2.w + v3.w);                   \
            accB.x += (v4.x + v5.x) + (v6.x + v7.x);                   \
            accB.y += (v4.y + v5.y) + (v6.y + v7.y);                   \
            accB.z += (v4.z + v5.z) + (v6.z + v7.z);                   \
            accB.w += (v4.w + v5.w) + (v6.w + v7.w);                   \
        } while (0)

    int e = 0;
    int nb = deg >> 3;                           // 8-edge blocks
    if (nb > 0) {
        int4 sa = *reinterpret_cast<const int4*>(row);       // 16B-aligned (CAP=64)
        int4 sb = *reinterpret_cast<const int4*>(row + 4);
        for (int i = 1; i < nb; i++) {
            int4 pa = *reinterpret_cast<const int4*>(row + i * 8);      // prefetch next block
            int4 pb = *reinterpret_cast<const int4*>(row + i * 8 + 4);
            PROC8(sa, sb);
            sa = pa; sb = pb;
        }
        PROC8(sa, sb);
        e = nb << 3;
    }
    #undef PROC8
    if (e + 4 <= deg) {                          // remaining quad
        int4 s4 = *reinterpret_cast<const int4*>(row + e);
        float4 v0 = xs4[s4.x * 8 + q];
        float4 v1 = xs4[s4.y * 8 + q];
        float4 v2 = xs4[s4.z * 8 + q];
        float4 v3 = xs4[s4.w * 8 + q];
        acc.x += (v0.x + v1.x) + (v2.x + v3.x);
        acc.y += (v0.y + v1.y) + (v2.y + v3.y);
        acc.z += (v0.z + v1.z) + (v2.z + v3.z);
        acc.w += (v0.w + v1.w) + (v2.w + v3.w);
        e += 4;
    }
    for (; e < deg; e++) {                       // scalar tail
        int s = row[e];
        float4 v = xs4[s * 8 + q];
        acc.x += v.x; acc.y += v.y; acc.z += v.z; acc.w += v.w;
    }
    acc.x += accB.x; acc.y += accB.y; acc.z += accB.z; acc.w += accB.w;

    // reset counter for the next graph replay (only the owner group reads cnt[n]
    // in this kernel; k_scale, the only other reader, has already completed)
    if (live && q == 0) g_cnt[n] = 0;

    float dn = rsqrtf((float)cnt + 1.0f);
    acc.x *= dn; acc.y *= dn; acc.z *= dn; acc.w *= dn;
    // acc = yf[4q .. 4q+3] of row layout [f=0..3][p=0..7]

    // ---- preload this lane's 4 hidden-channel weight columns ----
    int j0 = q * 4;
    float rMz[4][4], rMh[4][4], rcz[4], rch[4];
    #pragma unroll
    for (int i = 0; i < 4; i++) {
        rcz[i] = scz[j0 + i];
        rch[i] = sch[j0 + i];
        #pragma unroll
        for (int f = 0; f < 4; f++) {
            rMz[f][i] = sMz[f * 32 + j0 + i];
            rMh[f][i] = sMh[f * 32 + j0 + i];
        }
    }

    float Hacc[4] = {0.f, 0.f, 0.f, 0.f};
    #pragma unroll
    for (int p = 0; p < PER; p++) {
        float csel = (p & 3) == 0 ? acc.x : (p & 3) == 1 ? acc.y : (p & 3) == 2 ? acc.z : acc.w;
        int off = p >> 2;
        float y0 = __shfl_sync(0xffffffffu, csel, gbase + 0 + off);
        float y1 = __shfl_sync(0xffffffffu, csel, gbase + 2 + off);
        float y2 = __shfl_sync(0xffffffffu, csel, gbase + 4 + off);
        float y3 = __shfl_sync(0xffffffffu, csel, gbase + 6 + off);
        float pw = sp[p];   // = softmax(att)[p] / 2
        #pragma unroll
        for (int i = 0; i < 4; i++) {
            // azh = az/2 (0.5 folded into rMz/rcz); ah unscaled
            float azh = rcz[i] + y0 * rMz[0][i] + y1 * rMz[1][i] + y2 * rMz[2][i] + y3 * rMz[3][i];
            float ah  = rch[i] + y0 * rMh[0][i] + y1 * rMh[1][i] + y2 * rMh[2][i] + y3 * rMh[3][i];
            // sigmoid(-az)*tanh(ah) = 0.5*(1 - tanh(az/2))*tanh(ah); 0.5 folded into pw
            float t1 = tanh_fast(azh);
            float t2 = tanh_fast(ah);
            Hacc[i] += pw * (t2 - t1 * t2);
        }
    }

    // ---- output: partial o[8] over this lane's 4 channels, then 8-lane butterfly ----
    float o[PER];
    #pragma unroll
    for (int k = 0; k < PER; k++) o[k] = sOb[k] * 0.125f;   // split bias so 8-lane sum = bias
    #pragma unroll
    for (int i = 0; i < 4; i++) {
        float r = fmaxf(Hacc[i], 0.0f);
        #pragma unroll
        for (int k = 0; k < PER; k++) o[k] += r * sOW[(j0 + i) * 8 + k];
    }
    #pragma unroll
    for (int m = 1; m <= 4; m <<= 1) {
        #pragma unroll
        for (int k = 0; k < PER; k++)
            o[k] += __shfl_xor_sync(0xffffffffu, o[k], m);
    }
    float val = (q & 4) ? ((q & 2) ? ((q & 1) ? o[7] : o[6]) : ((q & 1) ? o[5] : o[4]))
                        : ((q & 2) ? ((q & 1) ? o[3] : o[2]) : ((q & 1) ? o[1] : o[0]));
    if (live) out[n * 8 + q] = val;
}

// ------------------------------------------------------------------
extern "C" void kernel_launch(void* const* d_in, const int* in_sizes, int n_in,
                              void* d_out, int out_size) {
    const float* x   = (const float*)d_in[0];
    const int* ei    = (const int*)d_in[1];
    const float* Wz  = (const float*)d_in[2];
    const float* bz  = (const float*)d_in[3];
    const float* Wh  = (const float*)d_in[6];
    const float* bh  = (const float*)d_in[7];
    const float* LzW = (const float*)d_in[8];
    const float* Lzb = (const float*)d_in[9];
    const float* LhW = (const float*)d_in[12];
    const float* Lhb = (const float*)d_in[13];
    const float* att = (const float*)d_in[14];
    const float* outW = (const float*)d_in[15];
    const float* outb = (const float*)d_in[16];
    float* out = (float*)d_out;

    const int* src = ei;             // edge_index[0,:]
    const int* dst = ei + N_EDGES;   // edge_index[1,:]

    k_fill<<<(N_EDGES + 255) / 256, 256>>>(src, dst, Wz, bz, Wh, bh,
                                           LzW, Lzb, LhW, Lhb, att);
    k_scale<<<(N_NODES * 8 + 255) / 256, 256>>>(x);
    k_fused<<<(N_NODES * 8 + 255) / 256, 256>>>(outW, outb, out);
}